// round 4
// baseline (speedup 1.0000x reference)
#include <cuda_runtime.h>
#include <cuda_bf16.h>

#define BIG 1e9f
#define FULLMASK 0xFFFFFFFFu

// One warp per image. Lane l owns rows r0=2l, r1=2l+1.
// Anti-diagonal wavefront t = i+j, t = 1..126. Potential transform:
//   z[i][j] = d[i][j] + 0.5*img[i][j]
//   z[i][j] = img[i][j] + min(z[i][j-1], z[i-1][j], z[i-1][j-1])
// Cell A=(r0, t-r0) needs: own A(t-1), left-lane B(t-1) [shfl], left B(t-2) [lagged shfl].
// Cell B=(r1, t-r1) needs: own B(t-1), own A(t-1), own A(t-2) — registers only.
// Not-yet-valid / expired cells carry ~BIG and never win a min (paths <= 128 << 1e9).
__global__ void __launch_bounds__(64) dp_wavefront_kernel(
    const float* __restrict__ img, float* __restrict__ out, int B)
{
    __shared__ float smem[2][4096];

    const int w = threadIdx.x >> 5;          // warp in block: 0..1
    const int lane = threadIdx.x & 31;
    const int img_idx = blockIdx.x * 2 + w;
    if (img_idx >= B) return;                 // warp-uniform

    float* sw = smem[w];

    // ---- stage image to shared (coalesced float4) ----
    {
        const float4* g = reinterpret_cast<const float4*>(img + (size_t)img_idx * 4096);
        float4* s4 = reinterpret_cast<float4*>(sw);
        #pragma unroll
        for (int k = 0; k < 32; k++)
            s4[k * 32 + lane] = g[k * 32 + lane];
        __syncwarp();
    }

    const int r0 = 2 * lane;
    const float* pA = sw + r0 * 64;       // row r0
    const float* pB = pA + 64;            // row r1

    // state at t=0: only cell (0,0) exists: z = 0.5*img[0][0]
    float zA1 = (lane == 0) ? 0.5f * sw[0] : BIG;  // own A at t-1
    float zA2 = BIG;                               // own A at t-2
    float zB1 = BIG;                               // own B at t-1
    float zL2 = BIG;                               // left B at t-2 (lagged shfl)

    int c_raw = -r0;      // column of cell A at t=0
    int offA = 0;         // clamp(c_raw, 0, 63)
    int offB = 0;         // = offA at previous step  (= clamp(colB))

    #pragma unroll 2
    for (int t = 1; t <= 126; t++) {
        float zL1 = __shfl_up_sync(FULLMASK, zB1, 1);   // left B at t-1
        if (lane == 0) zL1 = BIG;                        // row -1 doesn't exist

        c_raw++;
        offB = offA;                                     // colB(t) = colA(t-1)
        if ((unsigned)(c_raw - 1) < 63u) offA++;         // advance while 1..63

        float xA0 = pA[offA];    // img[r0][clamp(t-r0)]
        float xB0 = pB[offB];    // img[r1][clamp(t-r1)]

        float zAnew = xA0 + fminf(fminf(zA1, zL1), zL2);
        float zBnew = xB0 + fminf(fminf(zB1, zA1), zA2);

        zA2 = zA1; zA1 = zAnew;
        zB1 = zBnew;
        zL2 = zL1;
    }

    // d[63][63] = z[63][63] - 0.5*img[63][63]; cell (63,63) is lane 31's B
    if (lane == 31) out[img_idx] = zB1 - 0.5f * sw[4095];
}

extern "C" void kernel_launch(void* const* d_in, const int* in_sizes, int n_in,
                              void* d_out, int out_size) {
    const float* img = (const float*)d_in[0];
    float* out = (float*)d_out;
    int B = in_sizes[0] / (64 * 64);
    int blocks = (B + 1) / 2;           // 2 images per 64-thread block
    dp_wavefront_kernel<<<blocks, 64>>>(img, out, B);
}

// round 7
// speedup vs baseline: 2.2721x; 2.2721x over previous
#include <cuda_runtime.h>
#include <cuda_bf16.h>

#define BIG 1e9f
#define FULLMASK 0xFFFFFFFFu

// One warp per image, 2 images per 64-thread block. Lane l owns rows 2l, 2l+1.
// Anti-diagonal wavefront t = i+j = 1..126 with potential transform
//   z[i][j] = d[i][j] + 0.5*img[i][j] = img[i][j] + min(z_left, z_up, z_diag).
// Even rows in sA, odd rows in sB, row stride 65 (stride-2 coprime with 32)
// -> wavefront reads are bank-conflict-free: bank(A) = (t-l) mod 32.
__global__ void __launch_bounds__(64) dp_wavefront_kernel(
    const float* __restrict__ img, float* __restrict__ out, int B)
{
    // per image: sA[32][65] (rows 0,2,..62), sB[32][65] (rows 1,3,..63)
    __shared__ float smem[2][2 * 32 * 65];

    const int w = threadIdx.x >> 5;
    const int lane = threadIdx.x & 31;
    const int img_idx = blockIdx.x * 2 + w;
    if (img_idx >= B) return;                       // warp-uniform

    float* sA = smem[w];
    float* sB = smem[w] + 32 * 65;

    // ---- stage image (coalesced float4 LDG, scalar STS into padded rows) ----
    {
        const float4* g4 = reinterpret_cast<const float4*>(img + (size_t)img_idx * 4096);
        #pragma unroll
        for (int k = 0; k < 32; k++) {
            float4 v = g4[k * 32 + lane];
            int e = (k * 32 + lane) * 4;            // flat element index
            int r = e >> 6;                          // row 0..63
            int c = e & 63;                          // col, multiple of 4
            float* dst = ((r & 1) ? sB : sA) + (r >> 1) * 65 + c;
            dst[0] = v.x; dst[1] = v.y; dst[2] = v.z; dst[3] = v.w;
        }
        __syncwarp();
    }

    const float* bA = sA + lane * 65;   // row 2l
    const float* bB = sB + lane * 65;   // row 2l+1
    const int r0 = 2 * lane;

    // state: zA1/zA2 = own A at t-1/t-2; zB1 = own B at t-1; zL2 = left B at t-2
    float zA1 = (lane == 0) ? 0.5f * bA[0] : BIG;
    float zA2 = BIG;
    float zB1 = BIG;
    float zL2 = BIG;

    // prefetched image values for step t=1
    float xA = bA[min(63, max(0, 1 - r0))];
    float xB = bB[min(63, max(0, 0 - r0))];

    #pragma unroll 1
    for (int t = 1; t <= 126; t++) {
        float zL1 = __shfl_up_sync(FULLMASK, zB1, 1);    // left-lane B at t-1
        if (lane == 0) zL1 = BIG;

        // prefetch image values for step t+1 (offsets are pure functions of t)
        float nA = bA[min(63, max(0, t + 1 - r0))];
        float nB = bB[min(63, max(0, t - r0))];

        float zAnew = xA + fminf(fminf(zA1, zL1), zL2);
        float zBnew = xB + fminf(zB1, fminf(zA1, zA2));

        zA2 = zA1; zA1 = zAnew;
        zB1 = zBnew;
        zL2 = zL1;
        xA = nA; xB = nB;
    }

    // d[63][63] = z[63][63] - 0.5*img[63][63]; (63,63) is lane 31's B cell
    if (lane == 31) out[img_idx] = zB1 - 0.5f * bB[63];
}

extern "C" void kernel_launch(void* const* d_in, const int* in_sizes, int n_in,
                              void* d_out, int out_size) {
    const float* img = (const float*)d_in[0];
    float* out = (float*)d_out;
    int B = in_sizes[0] / (64 * 64);
    int blocks = (B + 1) / 2;            // 2 images per 64-thread block
    dp_wavefront_kernel<<<blocks, 64>>>(img, out, B);
}

// round 9
// speedup vs baseline: 3.9679x; 1.7464x over previous
#include <cuda_runtime.h>
#include <cuda_fp16.h>

#define BIG 1e9f
#define FULLMASK 0xFFFFFFFFu

// One warp per image, 2 images per 64-thread block. Lane l owns rows 2l, 2l+1.
// Anti-diagonal wavefront t = i+j = 1..126, potential transform
//   z[i][j] = d[i][j] + 0.5*img[i][j] = img[i][j] + min(z_left, z_up, z_diag).
// Image staged to smem as fp16 (z math stays fp32). Even rows in sA, odd in sB,
// row stride 68 halfwords -> wavefront LDS word = 33*l + f(t): conflict-free.
// No clamping: out-of-window cells carry ~1e9 (never win a min; paths <= 128),
// and all accessed indices are statically inside the two arrays (no NaN).
__global__ void __launch_bounds__(64) dp_wavefront_kernel(
    const float* __restrict__ img, float* __restrict__ out, int B)
{
    __shared__ __half smem[2][2 * 32 * 68];      // per image: sA[32][68], sB[32][68]

    const int w = threadIdx.x >> 5;
    const int lane = threadIdx.x & 31;
    const int img_idx = blockIdx.x * 2 + w;
    if (img_idx >= B) return;                     // warp-uniform

    __half* sA = smem[w];
    __half* sB = smem[w] + 32 * 68;

    // ---- stage image: float4 LDG -> packed half2 STS (row stride 68 halves) ----
    {
        const float4* g4 = reinterpret_cast<const float4*>(img + (size_t)img_idx * 4096);
        __half* base = (lane < 16) ? sA : sB;     // lanes 0-15: even rows; 16-31: odd
        const int s = lane & 15;                  // column group (4 floats)
        #pragma unroll 4
        for (int k = 0; k < 32; k++) {
            float4 v = g4[k * 32 + lane];         // element (row 2k+(lane>=16), col 4s..)
            __half2* d2 = reinterpret_cast<__half2*>(base + 68 * k + 4 * s);
            d2[0] = __floats2half2_rn(v.x, v.y);
            d2[1] = __floats2half2_rn(v.z, v.w);
        }
        __syncwarp();
    }

    // xA(t) = img[2l][t-2l]   = sA[68l + t-2l]   = pA[t],  pA = sA + 66l
    // xB(t) = img[2l+1][t-2l-1] = sB[68l + t-2l-1] = pB[t], pB = sB + 66l - 1
    const __half* pA = sA + 66 * lane;
    const __half* pB = sB + 66 * lane - 1;        // first deref is pB[1] >= sB[0]

    // state: zA1/zA2 = own A at t-1/t-2; zB1 = own B at t-1; zL2 = left B at t-2
    float zA1 = (lane == 0) ? 0.5f * __half2float(sA[0]) : BIG;
    float zA2 = BIG;
    float zB1 = BIG;
    float zL2 = BIG;

    // prefetched image values for step t=1
    float xA = __half2float(pA[1]);
    float xB = __half2float(pB[1]);

    #pragma unroll 4
    for (int t = 1; t <= 126; t++) {
        float zL1 = __shfl_up_sync(FULLMASK, zB1, 1);    // left-lane B at t-1
        if (lane == 0) zL1 = BIG;                         // row -1 doesn't exist

        // prefetch for t+1 (immediate offsets after unroll; max index in-bounds)
        float nA = __half2float(pA[t + 1]);
        float nB = __half2float(pB[t + 1]);

        float zAnew = xA + fminf(fminf(zA1, zL1), zL2);
        float zBnew = xB + fminf(zB1, fminf(zA1, zA2));

        zA2 = zA1; zA1 = zAnew;
        zB1 = zBnew;
        zL2 = zL1;
        xA = nA; xB = nB;
    }

    // d[63][63] = z[63][63] - 0.5*img[63][63]; (63,63) is lane 31's B cell = pB[126]
    if (lane == 31) out[img_idx] = zB1 - 0.5f * __half2float(pB[126]);
}

extern "C" void kernel_launch(void* const* d_in, const int* in_sizes, int n_in,
                              void* d_out, int out_size) {
    const float* img = (const float*)d_in[0];
    float* out = (float*)d_out;
    int B = in_sizes[0] / (64 * 64);
    int blocks = (B + 1) / 2;            // 2 images per 64-thread block
    dp_wavefront_kernel<<<blocks, 64>>>(img, out, B);
}